// round 4
// baseline (speedup 1.0000x reference)
#include <cuda_runtime.h>
#include <cuda_fp16.h>
#include <cstdint>

// ===================== problem constants =====================
#define BATCH 8192
#define INCH  4096
#define OUTCH 4096

// ===================== scratch (device globals; no allocs allowed) ==========
__device__ __half g_Xh[(size_t)BATCH * INCH];   // 64 MB: x in fp16
__device__ __half g_Wh[(size_t)OUTCH * INCH];   // 32 MB: densified W in fp16

// ===================== helpers =====================
__device__ __forceinline__ uint32_t smem_to_u32(const void* p) {
    uint32_t a;
    asm("{ .reg .u64 t; cvta.to.shared.u64 t, %1; cvt.u32.u64 %0, t; }"
        : "=r"(a) : "l"(p));
    return a;
}

// SW64 swizzle for 64-byte rows (8 rows x 64B atom): XOR bits[5:4] ^= bits[8:7]
__device__ __forceinline__ uint32_t swz64(uint32_t off) {
    return off ^ ((off >> 3) & 0x30);
}

__device__ __forceinline__ void ldsm_x4(uint32_t addr, uint32_t* r) {
    asm volatile("ldmatrix.sync.aligned.m8n8.x4.shared.b16 {%0,%1,%2,%3}, [%4];"
                 : "=r"(r[0]), "=r"(r[1]), "=r"(r[2]), "=r"(r[3]) : "r"(addr));
}

__device__ __forceinline__ void mma16816(float* c, const uint32_t* a, const uint32_t* b) {
    asm volatile(
        "mma.sync.aligned.m16n8k16.row.col.f32.f16.f16.f32 "
        "{%0,%1,%2,%3}, {%4,%5,%6,%7}, {%8,%9}, {%0,%1,%2,%3};"
        : "+f"(c[0]), "+f"(c[1]), "+f"(c[2]), "+f"(c[3])
        : "r"(a[0]), "r"(a[1]), "r"(a[2]), "r"(a[3]), "r"(b[0]), "r"(b[1]));
}

// ===================== GEMM configuration =====================
static constexpr int BM = 128;            // M tile (batch rows)
static constexpr int BN = 256;            // N tile (output channels)
static constexpr int BK = 32;             // K tile (halves) -> 64B rows
static constexpr int STAGES = 5;
static constexpr int NKT = INCH / BK;     // 128 K-tiles
static constexpr int THREADS = 256;

static constexpr uint32_t A_BYTES = BM * BK * 2;           // 8192
static constexpr uint32_t B_BYTES = BN * BK * 2;           // 16384
static constexpr uint32_t STAGE_BYTES = A_BYTES + B_BYTES; // 24576
static constexpr uint32_t SMEM_TOTAL = STAGES * STAGE_BYTES; // 122880

// ===================== preprocessing kernels =====================

// x [BATCH, INCH] fp32 -> g_Xh fp16 (float4 -> half2x2)
__global__ void __launch_bounds__(256) cvt_x_kernel(const float* __restrict__ x) {
    size_t i = (size_t)blockIdx.x * blockDim.x + threadIdx.x;  // float4 index
    float4 v = reinterpret_cast<const float4*>(x)[i];
    __half2 h0 = __floats2half2_rn(v.x, v.y);
    __half2 h1 = __floats2half2_rn(v.z, v.w);
    uint2 u;
    u.x = *reinterpret_cast<uint32_t*>(&h0);
    u.y = *reinterpret_cast<uint32_t*>(&h1);
    reinterpret_cast<uint2*>(g_Xh)[i] = u;
}

// zero g_Wh
__global__ void __launch_bounds__(256) zero_w_kernel() {
    size_t i = (size_t)blockIdx.x * blockDim.x + threadIdx.x;  // uint4 index
    reinterpret_cast<uint4*>(g_Wh)[i] = make_uint4(0u, 0u, 0u, 0u);
}

// scatter COO values into dense fp16 W
__global__ void __launch_bounds__(256) scat_w_kernel(const float* __restrict__ w,
                                                     const int* __restrict__ rows,
                                                     const int* __restrict__ cols,
                                                     int nnz) {
    int i = blockIdx.x * blockDim.x + threadIdx.x;
    if (i < nnz) {
        g_Wh[(size_t)rows[i] * INCH + (size_t)cols[i]] = __float2half_rn(w[i]);
    }
}

// ===================== GEMM: out = Xh @ Wh^T + bias =====================
// CTA 128x256, 8 warps of 64x64 (2m x 4n), BK=32, 5-stage cp.async pipeline.
__global__ void __launch_bounds__(THREADS, 1)
gemm_hmma_kernel(const float* __restrict__ bias, float* __restrict__ out) {
    extern __shared__ char smem[];
    const uint32_t sb = smem_to_u32(smem);
    const int tid = threadIdx.x;
    const int wid = tid >> 5;
    const int lane = tid & 31;
    const int m_base = blockIdx.y * BM;
    const int n_base = blockIdx.x * BN;
    const int wm = wid >> 2;      // 0..1 -> m offset wm*64
    const int wn = wid & 3;       // 0..3 -> n offset wn*64
    const int g = lane >> 2;      // group id (row within 8x8)
    const int tig = lane & 3;     // thread in group

    // ---- cp.async slot setup: 1536 x 16B chunks per K-tile, 6 per thread ----
    // chunks [0,512):   A, row = id/4 (128 rows x 4 chunks of 16B)
    // chunks [512,1536): B, row = (id-512)/4 (256 rows x 4 chunks)
    const __half* gsrc[6];
    uint32_t sdst[6];
    #pragma unroll
    for (int i = 0; i < 6; i++) {
        int id = i * THREADS + tid;
        if (id < 512) {
            int r = id >> 2, c = id & 3;
            gsrc[i] = g_Xh + (size_t)(m_base + r) * INCH + c * 8;
            sdst[i] = swz64((uint32_t)r * 64u + (uint32_t)c * 16u);
        } else {
            int id2 = id - 512;
            int r = id2 >> 2, c = id2 & 3;
            gsrc[i] = g_Wh + (size_t)(n_base + r) * INCH + c * 8;
            sdst[i] = A_BYTES + swz64((uint32_t)r * 64u + (uint32_t)c * 16u);
        }
    }

    auto issue_tile = [&](int t) {
        uint32_t stb = (uint32_t)(t % STAGES) * STAGE_BYTES;
        #pragma unroll
        for (int i = 0; i < 6; i++) {
            uint32_t d = sb + stb + sdst[i];
            const void* s = (const void*)(gsrc[i] + (size_t)t * BK);
            asm volatile("cp.async.cg.shared.global [%0], [%1], 16;"
                         :: "r"(d), "l"(s));
        }
    };

    // ---- prologue: stages 0..STAGES-2 ----
    #pragma unroll
    for (int t = 0; t < STAGES - 1; t++) {
        issue_tile(t);
        asm volatile("cp.async.commit_group;" ::: "memory");
    }

    // ---- per-lane invariant fragment address parts ----
    // A (X, [m][k] k-major), non-trans ldmatrix:
    //   lanes 0-15 -> m rows 0-15 @ k+0; lanes 16-31 -> m rows 0-15 @ k+16B
    const uint32_t a_row = (uint32_t)(wm * 64 + (lane & 15));
    const uint32_t a_kb  = (lane & 16) ? 16u : 0u;
    // B (W, [n][k] k-major), non-trans ldmatrix:
    //   matrix0 = n0-7@k0, matrix1 = n0-7@k+16B, matrix2 = n8-15@k0, matrix3 = n8-15@k+16B
    //   lanes 0-7 -> n0-7 k0 | 8-15 -> n0-7 k16B | 16-23 -> n8-15 k0 | 24-31 -> n8-15 k16B
    const uint32_t b_row = (uint32_t)(wn * 64 + (lane & 7) + ((lane & 16) ? 8 : 0));
    const uint32_t b_kb  = (lane & 8) ? 16u : 0u;

    float acc[4][8][4] = {};   // [m-tile][n-tile][c-frag]

    #pragma unroll 1
    for (int kt = 0; kt < NKT; kt++) {
        asm volatile("cp.async.wait_group %0;" :: "n"(STAGES - 2) : "memory");
        __syncthreads();

        // refill: stage (kt-1)%S was fully consumed in iteration kt-1
        int lt = kt + STAGES - 1;
        if (lt < NKT) issue_tile(lt);
        asm volatile("cp.async.commit_group;" ::: "memory");

        const uint32_t stb = sb + (uint32_t)(kt % STAGES) * STAGE_BYTES;

        #pragma unroll
        for (int k2 = 0; k2 < 2; k2++) {       // two k16 steps per BK=32
            const uint32_t koff = (uint32_t)k2 * 32u;
            uint32_t a[4][4];
            uint32_t b[8][2];
            #pragma unroll
            for (int mt = 0; mt < 4; mt++) {
                uint32_t off = (a_row + (uint32_t)mt * 16u) * 64u + koff + a_kb;
                ldsm_x4(stb + swz64(off), a[mt]);
            }
            #pragma unroll
            for (int bt = 0; bt < 4; bt++) {   // covers n-tiles 2bt, 2bt+1
                uint32_t off = (b_row + (uint32_t)bt * 16u) * 64u + koff + b_kb;
                uint32_t r[4];
                ldsm_x4(stb + A_BYTES + swz64(off), r);   // NON-trans: W is k-major
                b[2 * bt][0] = r[0]; b[2 * bt][1] = r[1];       // n group 0: {k0-7, k8-15}
                b[2 * bt + 1][0] = r[2]; b[2 * bt + 1][1] = r[3]; // n group 1
            }
            #pragma unroll
            for (int mt = 0; mt < 4; mt++)
                #pragma unroll
                for (int nt = 0; nt < 8; nt++)
                    mma16816(acc[mt][nt], a[mt], b[nt]);
        }
    }

    // ---- epilogue: direct stores + bias ----
    #pragma unroll
    for (int nt = 0; nt < 8; nt++) {
        const int col = n_base + wn * 64 + nt * 8 + 2 * tig;
        const float2 bv = __ldg(reinterpret_cast<const float2*>(bias + col));
        #pragma unroll
        for (int mt = 0; mt < 4; mt++) {
            const int r0 = m_base + wm * 64 + mt * 16 + g;
            float2 v0, v1;
            v0.x = acc[mt][nt][0] + bv.x;
            v0.y = acc[mt][nt][1] + bv.y;
            v1.x = acc[mt][nt][2] + bv.x;
            v1.y = acc[mt][nt][3] + bv.y;
            *reinterpret_cast<float2*>(out + (size_t)r0 * OUTCH + col) = v0;
            *reinterpret_cast<float2*>(out + (size_t)(r0 + 8) * OUTCH + col) = v1;
        }
    }
}

// ===================== launch =====================
extern "C" void kernel_launch(void* const* d_in, const int* in_sizes, int n_in,
                              void* d_out, int out_size) {
    (void)n_in; (void)out_size;
    const float* x    = (const float*)d_in[0];
    const float* w    = (const float*)d_in[1];
    const float* bias = (const float*)d_in[2];
    const int*   rows = (const int*)d_in[3];
    const int*   cols = (const int*)d_in[4];
    const int    nnz  = in_sizes[1];
    float* out = (float*)d_out;

    cudaFuncSetAttribute(gemm_hmma_kernel,
                         cudaFuncAttributeMaxDynamicSharedMemorySize, SMEM_TOTAL);

    // 1) x -> fp16
    {
        size_t n4 = (size_t)BATCH * INCH / 4;  // 8388608 float4s
        cvt_x_kernel<<<(unsigned)(n4 / 256), 256>>>(x);
    }
    // 2) zero dense W, then scatter COO values (fixed pattern -> deterministic)
    {
        size_t n16 = (size_t)OUTCH * INCH * sizeof(__half) / 16;  // 2097152 uint4s
        zero_w_kernel<<<(unsigned)(n16 / 256), 256>>>();
        scat_w_kernel<<<(nnz + 255) / 256, 256>>>(w, rows, cols, nnz);
    }
    // 3) dense fp16 HMMA GEMM + bias
    {
        dim3 grid(OUTCH / BN, BATCH / BM);  // (16, 64)
        gemm_hmma_kernel<<<grid, THREADS, SMEM_TOTAL>>>(bias, out);
    }
}

// round 7
// speedup vs baseline: 1.2206x; 1.2206x over previous
#include <cuda_runtime.h>
#include <cuda_fp16.h>
#include <cstdint>

// ===================== problem constants =====================
#define BATCH 8192
#define INCH  4096
#define OUTCH 4096

// ===================== scratch (device globals; no allocs allowed) ==========
__device__ __half g_Xh[(size_t)BATCH * INCH];   // 64 MB: x in fp16
__device__ __half g_Wh[(size_t)OUTCH * INCH];   // 32 MB: densified W in fp16

// ===================== helpers =====================
__device__ __forceinline__ uint32_t smem_to_u32(const void* p) {
    uint32_t a;
    asm("{ .reg .u64 t; cvta.to.shared.u64 t, %1; cvt.u32.u64 %0, t; }"
        : "=r"(a) : "l"(p));
    return a;
}

// SW128 swizzle for 128-byte rows (8 rows x 128B atom): bits[6:4] ^= bits[9:7]
__device__ __forceinline__ uint32_t swz128(uint32_t off) {
    return off ^ ((off >> 3) & 0x70);
}

__device__ __forceinline__ void ldsm_x4(uint32_t addr, uint32_t* r) {
    asm volatile("ldmatrix.sync.aligned.m8n8.x4.shared.b16 {%0,%1,%2,%3}, [%4];"
                 : "=r"(r[0]), "=r"(r[1]), "=r"(r[2]), "=r"(r[3]) : "r"(addr));
}

__device__ __forceinline__ void mma16816(float* c, const uint32_t* a, const uint32_t* b) {
    asm volatile(
        "mma.sync.aligned.m16n8k16.row.col.f32.f16.f16.f32 "
        "{%0,%1,%2,%3}, {%4,%5,%6,%7}, {%8,%9}, {%0,%1,%2,%3};"
        : "+f"(c[0]), "+f"(c[1]), "+f"(c[2]), "+f"(c[3])
        : "r"(a[0]), "r"(a[1]), "r"(a[2]), "r"(a[3]), "r"(b[0]), "r"(b[1]));
}

// ===================== GEMM configuration =====================
static constexpr int BM = 128;            // M tile
static constexpr int BN = 256;            // N tile
static constexpr int BK = 64;             // K tile (halves) -> 128B rows (SW128)
static constexpr int STAGES = 3;
static constexpr int NKT = INCH / BK;     // 64 K-tiles
static constexpr int THREADS = 256;

static constexpr uint32_t A_BYTES = BM * BK * 2;           // 16384
static constexpr uint32_t B_BYTES = BN * BK * 2;           // 32768
static constexpr uint32_t STAGE_BYTES = A_BYTES + B_BYTES; // 49152
static constexpr uint32_t SMEM_TOTAL = STAGES * STAGE_BYTES; // 147456

// ===================== preprocessing kernels =====================

__global__ void __launch_bounds__(256) cvt_x_kernel(const float* __restrict__ x) {
    size_t i = (size_t)blockIdx.x * blockDim.x + threadIdx.x;  // float4 index
    float4 v = reinterpret_cast<const float4*>(x)[i];
    __half2 h0 = __floats2half2_rn(v.x, v.y);
    __half2 h1 = __floats2half2_rn(v.z, v.w);
    uint2 u;
    u.x = *reinterpret_cast<uint32_t*>(&h0);
    u.y = *reinterpret_cast<uint32_t*>(&h1);
    reinterpret_cast<uint2*>(g_Xh)[i] = u;
}

__global__ void __launch_bounds__(256) zero_w_kernel() {
    size_t i = (size_t)blockIdx.x * blockDim.x + threadIdx.x;  // uint4 index
    reinterpret_cast<uint4*>(g_Wh)[i] = make_uint4(0u, 0u, 0u, 0u);
}

__global__ void __launch_bounds__(256) scat_w_kernel(const float* __restrict__ w,
                                                     const int* __restrict__ rows,
                                                     const int* __restrict__ cols,
                                                     int nnz) {
    int i = blockIdx.x * blockDim.x + threadIdx.x;
    if (i < nnz) {
        g_Wh[(size_t)rows[i] * INCH + (size_t)cols[i]] = __float2half_rn(w[i]);
    }
}

// ===================== GEMM: out = Xh @ Wh^T + bias =====================
// CTA 128x256, 8 warps of 64x64, BK=64, 3-stage cp.async pipeline,
// register double-buffered fragments (LDSM s+1 overlaps MMA s).
__global__ void __launch_bounds__(THREADS, 1)
gemm_hmma_kernel(const float* __restrict__ bias, float* __restrict__ out) {
    extern __shared__ char smem[];
    const uint32_t sb = smem_to_u32(smem);
    const int tid = threadIdx.x;
    const int wid = tid >> 5;
    const int lane = tid & 31;
    const int m_base = blockIdx.y * BM;
    const int n_base = blockIdx.x * BN;
    const int wm = wid >> 2;      // 0..1 -> m offset wm*64
    const int wn = wid & 3;       // 0..3 -> n offset wn*64
    const int g = lane >> 2;
    const int tig = lane & 3;

    // ---- cp.async mapping: 3072 x 16B chunks per K-tile, 12 per thread ----
    // A chunks (i=0..3):  row = i*32 + (tid>>3), col16 = tid&7
    // B chunks (i=0..7):  row = i*32 + (tid>>3), col16 = tid&7
    const int row_t = tid >> 3;
    const int col_t = tid & 7;
    const __half* gA = g_Xh + (size_t)(m_base + row_t) * INCH + col_t * 8;
    const __half* gB = g_Wh + (size_t)(n_base + row_t) * INCH + col_t * 8;
    uint32_t sdstA[4], sdstB[8];
    #pragma unroll
    for (int i = 0; i < 4; i++)
        sdstA[i] = swz128((uint32_t)(i * 32 + row_t) * 128u + (uint32_t)col_t * 16u);
    #pragma unroll
    for (int i = 0; i < 8; i++)
        sdstB[i] = A_BYTES + swz128((uint32_t)(i * 32 + row_t) * 128u + (uint32_t)col_t * 16u);

    auto issue_tile = [&](int t, int st) {
        uint32_t stb = sb + (uint32_t)st * STAGE_BYTES;
        #pragma unroll
        for (int i = 0; i < 4; i++) {
            const void* s = (const void*)(gA + (size_t)i * 32 * INCH + (size_t)t * BK);
            asm volatile("cp.async.cg.shared.global [%0], [%1], 16;"
                         :: "r"(stb + sdstA[i]), "l"(s));
        }
        #pragma unroll
        for (int i = 0; i < 8; i++) {
            const void* s = (const void*)(gB + (size_t)i * 32 * INCH + (size_t)t * BK);
            asm volatile("cp.async.cg.shared.global [%0], [%1], 16;"
                         :: "r"(stb + sdstB[i]), "l"(s));
        }
    };

    // ---- prologue: tiles 0,1 ----
    issue_tile(0, 0);
    asm volatile("cp.async.commit_group;" ::: "memory");
    issue_tile(1, 1);
    asm volatile("cp.async.commit_group;" ::: "memory");

    // ---- per-lane invariant fragment offsets (within stage, pre-swizzle) ----
    // A (X, [m][k] k-major), non-trans ldmatrix (layout verified in R4):
    const uint32_t a_row = (uint32_t)(wm * 64 + (lane & 15));
    const uint32_t a_kb  = (lane & 16) ? 16u : 0u;
    // B (W, [n][k] k-major), non-trans ldmatrix:
    const uint32_t b_row = (uint32_t)(wn * 64 + (lane & 7) + ((lane & 16) ? 8 : 0));
    const uint32_t b_kb  = (lane & 8) ? 16u : 0u;

    uint32_t a_off[4], b_off[4];
    #pragma unroll
    for (int mt = 0; mt < 4; mt++) a_off[mt] = (a_row + (uint32_t)mt * 16u) * 128u + a_kb;
    #pragma unroll
    for (int bt = 0; bt < 4; bt++) b_off[bt] = (b_row + (uint32_t)bt * 16u) * 128u + b_kb;

    float acc[4][8][4] = {};        // 128 regs
    uint32_t a_f[2][4][4];          // double-buffered A frags
    uint32_t b_f[2][8][2];          // double-buffered B frags

    auto load_step = [&](uint32_t stb, int s, int buf) {
        const uint32_t koff = (uint32_t)s * 32u;
        #pragma unroll
        for (int mt = 0; mt < 4; mt++)
            ldsm_x4(stb + swz128(a_off[mt] + koff), a_f[buf][mt]);
        #pragma unroll
        for (int bt = 0; bt < 4; bt++) {
            uint32_t r[4];
            ldsm_x4(stb + A_BYTES + swz128(b_off[bt] + koff), r);
            b_f[buf][2 * bt][0] = r[0]; b_f[buf][2 * bt][1] = r[1];
            b_f[buf][2 * bt + 1][0] = r[2]; b_f[buf][2 * bt + 1][1] = r[3];
        }
    };

    auto mma_step = [&](int buf) {
        #pragma unroll
        for (int mt = 0; mt < 4; mt++)
            #pragma unroll
            for (int nt = 0; nt < 8; nt++)
                mma16816(acc[mt][nt], a_f[buf][mt], b_f[buf][nt]);
    };

    int st_cmp = 0, st_load = 2;
    #pragma unroll 1
    for (int kt = 0; kt < NKT; kt++) {
        asm volatile("cp.async.wait_group 1;" ::: "memory");  // tile kt resident
        __syncthreads();

        const uint32_t stb = sb + (uint32_t)st_cmp * STAGE_BYTES;
        load_step(stb, 0, 0);

        // refill stage st_load (= stage consumed in iteration kt-1)
        if (kt + 2 < NKT) issue_tile(kt + 2, st_load);
        asm volatile("cp.async.commit_group;" ::: "memory");

        // 4 k16 steps, frags double-buffered: LDSM(s+1) overlaps MMA(s)
        load_step(stb, 1, 1);
        mma_step(0);
        load_step(stb, 2, 0);
        mma_step(1);
        load_step(stb, 3, 1);
        mma_step(0);
        mma_step(1);

        st_cmp  = (st_cmp  == STAGES - 1) ? 0 : st_cmp + 1;
        st_load = (st_load == STAGES - 1) ? 0 : st_load + 1;
    }

    // ---- epilogue: direct stores + bias ----
    #pragma unroll
    for (int nt = 0; nt < 8; nt++) {
        const int col = n_base + wn * 64 + nt * 8 + 2 * tig;
        const float2 bv = __ldg(reinterpret_cast<const float2*>(bias + col));
        #pragma unroll
        for (int mt = 0; mt < 4; mt++) {
            const int r0 = m_base + wm * 64 + mt * 16 + g;
            float2 v0, v1;
            v0.x = acc[mt][nt][0] + bv.x;
            v0.y = acc[mt][nt][1] + bv.y;
            v1.x = acc[mt][nt][2] + bv.x;
            v1.y = acc[mt][nt][3] + bv.y;
            *reinterpret_cast<float2*>(out + (size_t)r0 * OUTCH + col) = v0;
            *reinterpret_cast<float2*>(out + (size_t)(r0 + 8) * OUTCH + col) = v1;
        }
    }
}

// ===================== launch =====================
extern "C" void kernel_launch(void* const* d_in, const int* in_sizes, int n_in,
                              void* d_out, int out_size) {
    (void)n_in; (void)out_size;
    const float* x    = (const float*)d_in[0];
    const float* w    = (const float*)d_in[1];
    const float* bias = (const float*)d_in[2];
    const int*   rows = (const int*)d_in[3];
    const int*   cols = (const int*)d_in[4];
    const int    nnz  = in_sizes[1];
    float* out = (float*)d_out;

    cudaFuncSetAttribute(gemm_hmma_kernel,
                         cudaFuncAttributeMaxDynamicSharedMemorySize, SMEM_TOTAL);

    // 1) x -> fp16
    {
        size_t n4 = (size_t)BATCH * INCH / 4;
        cvt_x_kernel<<<(unsigned)(n4 / 256), 256>>>(x);
    }
    // 2) zero dense W, then scatter COO values (fixed pattern -> deterministic)
    {
        size_t n16 = (size_t)OUTCH * INCH * sizeof(__half) / 16;
        zero_w_kernel<<<(unsigned)(n16 / 256), 256>>>();
        scat_w_kernel<<<(nnz + 255) / 256, 256>>>(w, rows, cols, nnz);
    }
    // 3) dense fp16 HMMA GEMM + bias
    {
        dim3 grid(OUTCH / BN, BATCH / BM);  // (16, 64)
        gemm_hmma_kernel<<<grid, THREADS, SMEM_TOTAL>>>(bias, out);
    }
}

// round 10
// speedup vs baseline: 1.4660x; 1.2010x over previous
#include <cuda_runtime.h>
#include <cuda_fp16.h>
#include <cstdint>

// ===================== problem constants =====================
#define BATCH 8192
#define INCH  4096
#define OUTCH 4096

// ===================== scratch (device globals; no allocs allowed) ==========
__device__ __half g_Xh[(size_t)BATCH * INCH];   // 64 MB: x in fp16
__device__ __half g_Wh[(size_t)OUTCH * INCH];   // 32 MB: densified W in fp16

// ===================== helpers =====================
__device__ __forceinline__ uint32_t smem_to_u32(const void* p) {
    uint32_t a;
    asm("{ .reg .u64 t; cvta.to.shared.u64 t, %1; cvt.u32.u64 %0, t; }"
        : "=r"(a) : "l"(p));
    return a;
}

// SW128 swizzle for 128-byte rows (8 rows x 128B atom): bits[6:4] ^= bits[9:7]
__device__ __forceinline__ uint32_t swz128(uint32_t off) {
    return off ^ ((off >> 3) & 0x70);
}

__device__ __forceinline__ void ldsm_x4(uint32_t addr, uint32_t* r) {
    asm volatile("ldmatrix.sync.aligned.m8n8.x4.shared.b16 {%0,%1,%2,%3}, [%4];"
                 : "=r"(r[0]), "=r"(r[1]), "=r"(r[2]), "=r"(r[3]) : "r"(addr));
}

__device__ __forceinline__ void mma16816(float* c, const uint32_t* a, const uint32_t* b) {
    asm volatile(
        "mma.sync.aligned.m16n8k16.row.col.f32.f16.f16.f32 "
        "{%0,%1,%2,%3}, {%4,%5,%6,%7}, {%8,%9}, {%0,%1,%2,%3};"
        : "+f"(c[0]), "+f"(c[1]), "+f"(c[2]), "+f"(c[3])
        : "r"(a[0]), "r"(a[1]), "r"(a[2]), "r"(a[3]), "r"(b[0]), "r"(b[1]));
}

// ===================== GEMM configuration =====================
// CTA 128x128, 4 warps of 64x64, 128 threads, 2 CTAs/SM (decorrelated barriers).
static constexpr int BM = 128;            // M tile
static constexpr int BN = 128;            // N tile
static constexpr int BK = 64;             // K tile (halves) -> 128B rows (SW128)
static constexpr int STAGES = 3;
static constexpr int NKT = INCH / BK;     // 64 K-tiles
static constexpr int THREADS = 128;

static constexpr uint32_t A_BYTES = BM * BK * 2;           // 16384
static constexpr uint32_t B_BYTES = BN * BK * 2;           // 16384
static constexpr uint32_t STAGE_BYTES = A_BYTES + B_BYTES; // 32768
static constexpr uint32_t SMEM_TOTAL = STAGES * STAGE_BYTES; // 98304 (x2 CTAs = 192KB/SM)

// ===================== preprocessing kernels =====================

__global__ void __launch_bounds__(256) cvt_x_kernel(const float* __restrict__ x) {
    size_t i = (size_t)blockIdx.x * blockDim.x + threadIdx.x;  // float4 index
    float4 v = reinterpret_cast<const float4*>(x)[i];
    __half2 h0 = __floats2half2_rn(v.x, v.y);
    __half2 h1 = __floats2half2_rn(v.z, v.w);
    uint2 u;
    u.x = *reinterpret_cast<uint32_t*>(&h0);
    u.y = *reinterpret_cast<uint32_t*>(&h1);
    reinterpret_cast<uint2*>(g_Xh)[i] = u;
}

__global__ void __launch_bounds__(256) zero_w_kernel() {
    size_t i = (size_t)blockIdx.x * blockDim.x + threadIdx.x;  // uint4 index
    reinterpret_cast<uint4*>(g_Wh)[i] = make_uint4(0u, 0u, 0u, 0u);
}

__global__ void __launch_bounds__(256) scat_w_kernel(const float* __restrict__ w,
                                                     const int* __restrict__ rows,
                                                     const int* __restrict__ cols,
                                                     int nnz) {
    int i = blockIdx.x * blockDim.x + threadIdx.x;
    if (i < nnz) {
        g_Wh[(size_t)rows[i] * INCH + (size_t)cols[i]] = __float2half_rn(w[i]);
    }
}

// ===================== GEMM: out = Xh @ Wh^T + bias =====================
__global__ void __launch_bounds__(THREADS, 2)
gemm_hmma_kernel(const float* __restrict__ bias, float* __restrict__ out) {
    extern __shared__ char smem[];
    const uint32_t sb = smem_to_u32(smem);
    const int tid = threadIdx.x;
    const int wid = tid >> 5;
    const int lane = tid & 31;
    const int m_base = blockIdx.y * BM;
    const int n_base = blockIdx.x * BN;
    const int wm = wid >> 1;      // 0..1 -> m offset wm*64
    const int wn = wid & 1;       // 0..1 -> n offset wn*64
    const int g = lane >> 2;
    const int tig = lane & 3;

    // ---- cp.async mapping: 2048 x 16B chunks per K-tile, 16 per thread ----
    // A chunks (i=0..7): row = i*16 + (tid>>3), col16 = tid&7
    // B chunks (i=0..7): row = i*16 + (tid>>3), col16 = tid&7
    const int row_t = tid >> 3;   // 0..15
    const int col_t = tid & 7;
    const __half* gA = g_Xh + (size_t)(m_base + row_t) * INCH + col_t * 8;
    const __half* gB = g_Wh + (size_t)(n_base + row_t) * INCH + col_t * 8;
    uint32_t sdstA[8], sdstB[8];
    #pragma unroll
    for (int i = 0; i < 8; i++) {
        sdstA[i] = swz128((uint32_t)(i * 16 + row_t) * 128u + (uint32_t)col_t * 16u);
        sdstB[i] = A_BYTES + swz128((uint32_t)(i * 16 + row_t) * 128u + (uint32_t)col_t * 16u);
    }

    auto issue_tile = [&](int t, int st) {
        uint32_t stb = sb + (uint32_t)st * STAGE_BYTES;
        #pragma unroll
        for (int i = 0; i < 8; i++) {
            const void* s = (const void*)(gA + (size_t)i * 16 * INCH + (size_t)t * BK);
            asm volatile("cp.async.cg.shared.global [%0], [%1], 16;"
                         :: "r"(stb + sdstA[i]), "l"(s));
        }
        #pragma unroll
        for (int i = 0; i < 8; i++) {
            const void* s = (const void*)(gB + (size_t)i * 16 * INCH + (size_t)t * BK);
            asm volatile("cp.async.cg.shared.global [%0], [%1], 16;"
                         :: "r"(stb + sdstB[i]), "l"(s));
        }
    };

    // ---- prologue: tiles 0,1 ----
    issue_tile(0, 0);
    asm volatile("cp.async.commit_group;" ::: "memory");
    issue_tile(1, 1);
    asm volatile("cp.async.commit_group;" ::: "memory");

    // ---- per-lane invariant fragment offsets (layouts verified in R4/R7) ----
    // A (X, [m][k] k-major), non-trans ldmatrix:
    const uint32_t a_row = (uint32_t)(wm * 64 + (lane & 15));
    const uint32_t a_kb  = (lane & 16) ? 16u : 0u;
    // B (W, [n][k] k-major), non-trans ldmatrix:
    const uint32_t b_row = (uint32_t)(wn * 64 + (lane & 7) + ((lane & 16) ? 8 : 0));
    const uint32_t b_kb  = (lane & 8) ? 16u : 0u;

    uint32_t a_off[4], b_off[4];
    #pragma unroll
    for (int mt = 0; mt < 4; mt++) a_off[mt] = (a_row + (uint32_t)mt * 16u) * 128u + a_kb;
    #pragma unroll
    for (int bt = 0; bt < 4; bt++) b_off[bt] = (b_row + (uint32_t)bt * 16u) * 128u + b_kb;

    float acc[4][8][4] = {};        // 128 regs
    uint32_t a_f[2][4][4];          // double-buffered A frags
    uint32_t b_f[2][8][2];          // double-buffered B frags

    auto load_step = [&](uint32_t stb, int s, int buf) {
        const uint32_t koff = (uint32_t)s * 32u;
        #pragma unroll
        for (int mt = 0; mt < 4; mt++)
            ldsm_x4(stb + swz128(a_off[mt] + koff), a_f[buf][mt]);
        #pragma unroll
        for (int bt = 0; bt < 4; bt++) {
            uint32_t r[4];
            ldsm_x4(stb + A_BYTES + swz128(b_off[bt] + koff), r);
            b_f[buf][2 * bt][0] = r[0]; b_f[buf][2 * bt][1] = r[1];
            b_f[buf][2 * bt + 1][0] = r[2]; b_f[buf][2 * bt + 1][1] = r[3];
        }
    };

    auto mma_step = [&](int buf) {
        #pragma unroll
        for (int mt = 0; mt < 4; mt++)
            #pragma unroll
            for (int nt = 0; nt < 8; nt++)
                mma16816(acc[mt][nt], a_f[buf][mt], b_f[buf][nt]);
    };

    int st_cmp = 0, st_load = 2;
    #pragma unroll 1
    for (int kt = 0; kt < NKT; kt++) {
        asm volatile("cp.async.wait_group 1;" ::: "memory");  // tile kt resident
        __syncthreads();

        const uint32_t stb = sb + (uint32_t)st_cmp * STAGE_BYTES;
        load_step(stb, 0, 0);

        // refill stage st_load (= stage consumed in iteration kt-1)
        if (kt + 2 < NKT) issue_tile(kt + 2, st_load);
        asm volatile("cp.async.commit_group;" ::: "memory");

        // 4 k16 steps, frags double-buffered: LDSM(s+1) overlaps MMA(s)
        load_step(stb, 1, 1);
        mma_step(0);
        load_step(stb, 2, 0);
        mma_step(1);
        load_step(stb, 3, 1);
        mma_step(0);
        mma_step(1);

        st_cmp  = (st_cmp  == STAGES - 1) ? 0 : st_cmp + 1;
        st_load = (st_load == STAGES - 1) ? 0 : st_load + 1;
    }

    // ---- epilogue: direct stores + bias ----
    #pragma unroll
    for (int nt = 0; nt < 8; nt++) {
        const int col = n_base + wn * 64 + nt * 8 + 2 * tig;
        const float2 bv = __ldg(reinterpret_cast<const float2*>(bias + col));
        #pragma unroll
        for (int mt = 0; mt < 4; mt++) {
            const int r0 = m_base + wm * 64 + mt * 16 + g;
            float2 v0, v1;
            v0.x = acc[mt][nt][0] + bv.x;
            v0.y = acc[mt][nt][1] + bv.y;
            v1.x = acc[mt][nt][2] + bv.x;
            v1.y = acc[mt][nt][3] + bv.y;
            *reinterpret_cast<float2*>(out + (size_t)r0 * OUTCH + col) = v0;
            *reinterpret_cast<float2*>(out + (size_t)(r0 + 8) * OUTCH + col) = v1;
        }
    }
}

// ===================== launch =====================
extern "C" void kernel_launch(void* const* d_in, const int* in_sizes, int n_in,
                              void* d_out, int out_size) {
    (void)n_in; (void)out_size;
    const float* x    = (const float*)d_in[0];
    const float* w    = (const float*)d_in[1];
    const float* bias = (const float*)d_in[2];
    const int*   rows = (const int*)d_in[3];
    const int*   cols = (const int*)d_in[4];
    const int    nnz  = in_sizes[1];
    float* out = (float*)d_out;

    cudaFuncSetAttribute(gemm_hmma_kernel,
                         cudaFuncAttributeMaxDynamicSharedMemorySize, SMEM_TOTAL);

    // 1) x -> fp16
    {
        size_t n4 = (size_t)BATCH * INCH / 4;
        cvt_x_kernel<<<(unsigned)(n4 / 256), 256>>>(x);
    }
    // 2) zero dense W, then scatter COO values (fixed pattern -> deterministic)
    {
        size_t n16 = (size_t)OUTCH * INCH * sizeof(__half) / 16;
        zero_w_kernel<<<(unsigned)(n16 / 256), 256>>>();
        scat_w_kernel<<<(nnz + 255) / 256, 256>>>(w, rows, cols, nnz);
    }
    // 3) dense fp16 HMMA GEMM + bias (2048 CTAs, 2 per SM)
    {
        dim3 grid(OUTCH / BN, BATCH / BM);  // (32, 64)
        gemm_hmma_kernel<<<grid, THREADS, SMEM_TOTAL>>>(bias, out);
    }
}